// round 1
// baseline (speedup 1.0000x reference)
#include <cuda_runtime.h>

#define NBLK 2048
#define NTHR 256

// Block partial sums — device-global scratch (no allocation allowed in kernel_launch).
__device__ float g_partials[NBLK];

__device__ __forceinline__ float kl_elem(float p, float q) {
    // KL(p||q) = p*(log p - log q) + (1-p)*(log(1-p) - log(1-q))
    // Inputs are bounded in [1e-4, 1-1e-4], so 1-p / 1-q are safe in fp32 and
    // __logf (~2^-21 rel err) is far inside the 1e-3 tolerance.
    float omp = 1.0f - p;
    float omq = 1.0f - q;
    float lp  = __logf(p);
    float lq  = __logf(q);
    float l1p = __logf(omp);
    float l1q = __logf(omq);
    return p * (lp - lq) + omp * (l1p - l1q);
}

__global__ void __launch_bounds__(NTHR)
kl_stage1(const float* __restrict__ p, const float* __restrict__ q, int n) {
    const int nvec   = n >> 2;          // float4 count
    const int tid    = blockIdx.x * NTHR + threadIdx.x;
    const int stride = gridDim.x * NTHR;

    const float4* __restrict__ p4 = reinterpret_cast<const float4*>(p);
    const float4* __restrict__ q4 = reinterpret_cast<const float4*>(q);

    float acc = 0.0f;
    for (int i = tid; i < nvec; i += stride) {
        float4 a = p4[i];
        float4 b = q4[i];
        acc += kl_elem(a.x, b.x);
        acc += kl_elem(a.y, b.y);
        acc += kl_elem(a.z, b.z);
        acc += kl_elem(a.w, b.w);
    }

    // Scalar tail (n not divisible by 4): first few threads grab one element each.
    int tail_base = nvec << 2;
    int tail_idx  = tail_base + tid;
    if (tail_idx < n) {
        acc += kl_elem(p[tail_idx], q[tail_idx]);
    }

    // Warp reduce
    #pragma unroll
    for (int o = 16; o > 0; o >>= 1)
        acc += __shfl_down_sync(0xffffffffu, acc, o);

    __shared__ float s[NTHR / 32];
    if ((threadIdx.x & 31) == 0)
        s[threadIdx.x >> 5] = acc;
    __syncthreads();

    if (threadIdx.x < 32) {
        float v = (threadIdx.x < NTHR / 32) ? s[threadIdx.x] : 0.0f;
        #pragma unroll
        for (int o = (NTHR / 64); o > 0; o >>= 1)
            v += __shfl_down_sync(0xffffffffu, v, o);
        if (threadIdx.x == 0)
            g_partials[blockIdx.x] = v;
    }
}

__global__ void __launch_bounds__(256)
kl_stage2(float* __restrict__ out) {
    __shared__ double s[256];
    double acc = 0.0;
    for (int i = threadIdx.x; i < NBLK; i += 256)
        acc += (double)g_partials[i];
    s[threadIdx.x] = acc;
    __syncthreads();
    #pragma unroll
    for (int o = 128; o > 0; o >>= 1) {
        if (threadIdx.x < o) s[threadIdx.x] += s[threadIdx.x + o];
        __syncthreads();
    }
    if (threadIdx.x == 0)
        out[0] = (float)s[0];
}

extern "C" void kernel_launch(void* const* d_in, const int* in_sizes, int n_in,
                              void* d_out, int out_size) {
    const float* p = (const float*)d_in[0];
    const float* q = (const float*)d_in[1];
    float* out = (float*)d_out;
    int n = in_sizes[0];

    kl_stage1<<<NBLK, NTHR>>>(p, q, n);
    kl_stage2<<<1, 256>>>(out);
}